// round 6
// baseline (speedup 1.0000x reference)
#include <cuda_runtime.h>

typedef unsigned long long u64;
typedef unsigned int u32;

#define DD 1024
#define BB 64
#define BETA_W 0.001f

__device__ __forceinline__ u64 ce_sel(u64 a, u64 b, bool takeMax) {
    return takeMax ? (a > b ? a : b) : (a < b ? a : b);
}

// 2-sync block inclusive add-scan (dedicated partials array per call site!)
__device__ __forceinline__ int bscan_add(int v, int tid, int lane, int wrp, int* part) {
    int inc = v;
    #pragma unroll
    for (int o = 1; o < 32; o <<= 1) {
        int t = __shfl_up_sync(0xffffffffu, inc, o);
        if (lane >= o) inc += t;
    }
    if (lane == 31) part[wrp] = inc;
    __syncthreads();
    if (tid < 32) {
        int p = part[tid];
        #pragma unroll
        for (int o = 1; o < 32; o <<= 1) {
            int t = __shfl_up_sync(0xffffffffu, p, o);
            if (tid >= o) p += t;
        }
        part[tid] = p;
    }
    __syncthreads();
    if (wrp > 0) inc += part[wrp - 1];
    return inc;
}

// Junction cascade over a gapped block array with edge pointers.
// b: {sum,cnt} blocks, cnt==0 => dead. jl[b_edge]=next valid left, jr[a_edge]=next valid right.
__device__ void cascade(float2* b, int* jl, int* jr, int ls, int junc, int re) {
    int li = junc - 1;
    float2 L = b[li];
    if (L.y == 0.0f) { li = jl[li]; L = b[li]; }   // single jump lands valid (invariant)
    float2 P = b[junc];                             // segment start: always valid
    if (!(L.x * P.y < P.x * L.y)) return;           // no junction violation
    P.x += L.x; P.y += L.y;
    b[li].y = 0.0f;
    b[junc].y = 0.0f;
    int lpos = li;            // leftmost absorbed slot (P's home)
    int lc = li - 1;
    int rc = junc + 1;
    int lstop = ls - 1;       // valid left stopper (or ls-1 when absorbed to ls)
    int rstop = re;           // valid right stopper (or re)
    bool changed = true;
    while (changed) {
        changed = false;
        while (lc >= ls) {
            float2 Lb = b[lc];
            if (Lb.y == 0.0f) { lc = jl[lc]; if (lc < ls) break; Lb = b[lc]; }
            if (Lb.x * P.y < P.x * Lb.y) {
                P.x += Lb.x; P.y += Lb.y;
                b[lc].y = 0.0f;
                lpos = lc; --lc; changed = true;
            } else { lstop = lc; break; }
        }
        while (rc < re) {
            float2 Rb = b[rc];
            if (Rb.y == 0.0f) { rc = jr[rc]; if (rc >= re) break; Rb = b[rc]; }
            if (Rb.x * P.y > P.x * Rb.y) {
                P.x += Rb.x; P.y += Rb.y;
                b[rc].y = 0.0f;
                ++rc; changed = true;
            } else { rstop = rc; break; }
        }
    }
    b[lpos] = P;
    if (lpos - 1 > lstop) { jl[lpos - 1] = lstop; jr[lstop + 1] = lpos; }
    if (rstop - 1 > lpos) { jl[rstop - 1] = lpos; jr[lpos + 1] = rstop; }
}

__global__ __launch_bounds__(1024) void oscarmax_kernel(const float* __restrict__ x,
                                                        float* __restrict__ out) {
    __shared__ u64   sbuf[2][DD];      // sort buffers; after sort: bA (8KB) + jl/jr (8KB)
    __shared__ float sy[DD];           // s values (isotonic input)
    __shared__ float mval[DD];         // pool value at block-start positions
    __shared__ float sgn_mark[DD];     // sign(x); then markerpos (int view)
    __shared__ float zcs[DD];          // sorted z, then cumsum
    __shared__ int   part_a[32];       // expansion scan
    __shared__ int   part_b[32];       // fill max-scan
    __shared__ int   part_c[32];       // rank scan
    __shared__ float part_d[32];       // cumsum scan

    int*    markerpos = (int*)sgn_mark;
    float2* bA = (float2*)sbuf;            // 1024 blocks
    int*    jl = (int*)&sbuf[1][0];        // 1024 ints
    int*    jr = jl + DD;                  // 1024 ints

    const int tid  = threadIdx.x;
    const int lane = tid & 31;
    const int wrp  = tid >> 5;
    const int row  = blockIdx.x;

    // ---- load, sign, pack sortable u64 (|x| desc, idx asc tiebreak) ----
    float xv = x[row * DD + tid];
    sgn_mark[tid] = (xv > 0.0f) ? 1.0f : ((xv < 0.0f) ? -1.0f : 0.0f);
    u32 kb = __float_as_uint(fabsf(xv));
    u64 v = ((u64)kb << 32) | (u32)(~(u32)tid);

    // ---- bitonic sort (descending) ----
    #pragma unroll
    for (int k = 2; k <= 32; k <<= 1) {
        #pragma unroll
        for (int j = k >> 1; j > 0; j >>= 1) {
            u64 o = __shfl_xor_sync(0xffffffffu, v, j);
            bool lower = ((tid & j) == 0);
            bool dec   = ((tid & k) == 0);
            v = ce_sel(v, o, lower == dec);
        }
    }
    int cur = 0;
    sbuf[0][tid] = v;
    __syncthreads();
    #pragma unroll 1
    for (int k = 64; k <= 1024; k <<= 1) {
        #pragma unroll 1
        for (int j = k >> 1; j >= 32; j >>= 1) {
            u64 o = sbuf[cur][tid ^ j];
            bool lower = ((tid & j) == 0);
            bool dec   = ((tid & k) == 0);
            v = ce_sel(v, o, lower == dec);
            sbuf[cur ^ 1][tid] = v;
            __syncthreads();
            cur ^= 1;
        }
        #pragma unroll
        for (int j = 16; j > 0; j >>= 1) {
            u64 o = __shfl_xor_sync(0xffffffffu, v, j);
            bool lower = ((tid & j) == 0);
            bool dec   = ((tid & k) == 0);
            v = ce_sel(v, o, lower == dec);
        }
        if (k < 1024) {
            sbuf[cur ^ 1][tid] = v;
            __syncthreads();
            cur ^= 1;
        }
    }

    // ---- unpack, gather sign, write s ----
    float keyf  = __uint_as_float((u32)(v >> 32));
    int   idx   = (int)(~((u32)v));
    float sgn_i = sgn_mark[idx];            // all sgn reads complete before next sync
    sy[tid] = keyf - BETA_W * (float)(DD - 1 - tid);
    __syncthreads();     // sy visible; sort buffer dead -> bA / jl / jr

    // ---- level 1: per-chunk PAVA (32 chunks x 32 elems), lane 0 of each warp ----
    if (lane == 0) {
        const int base = wrp << 5;
        float2* cb = bA + base;
        int nb = 0;
        float ts = sy[base], tc = 1.0f;
        #pragma unroll 1
        for (int i = 1; i < 32; i++) {
            float cs = sy[base + i], cc = 1.0f;
            for (;;) {
                if (cs * tc > ts * cc) {
                    cs += ts; cc += tc;
                    if (nb > 0) { --nb; ts = cb[nb].x; tc = cb[nb].y; }
                    else        { ts = cs; tc = cc; goto nexti; }
                } else break;
            }
            cb[nb++] = make_float2(ts, tc);
            ts = cs; tc = cc;
            nexti: ;
        }
        cb[nb++] = make_float2(ts, tc);
        // kill unused tail slots + set the run's edge pointers
        for (int q = nb; q < 32; q++) cb[q].y = 0.0f;
        if (nb < 32) {
            jl[base + 31] = base + nb - 1;
            jr[base + nb] = base + 32;     // next chunk start (1024 sentinel for last)
        }
    }
    markerpos[tid] = -1;                   // repurpose sgn_mark (reads done pre-sync)
    __syncthreads();

    // ---- merge tree: 5 cascade levels entirely inside warp 0 ----
    if (wrp == 0) {
        #pragma unroll 1
        for (int L = 0; L < 5; L++) {
            int npairs = 16 >> L;
            if (lane < npairs) {
                int seg = 64 << L;
                int ls  = lane * seg;
                cascade(bA, jl, jr, ls, ls + (seg >> 1), ls + seg);
            }
            __syncwarp();
        }
    }
    __syncthreads();

    // ---- parallel expansion: block starts via prefix scan of counts ----
    float2 bfin = bA[tid];
    int cnt = (int)bfin.y;
    int incc = bscan_add(cnt, tid, lane, wrp, part_a);
    int start = incc - cnt;
    if (cnt > 0) {
        mval[start] = fmaxf(bfin.x / bfin.y, 0.0f);
        markerpos[start] = start;
    }
    __syncthreads();

    // ---- fill-forward: block inclusive max-scan of markerpos (2 syncs) ----
    int mp = markerpos[tid];
    #pragma unroll
    for (int o = 1; o < 32; o <<= 1) {
        int t = __shfl_up_sync(0xffffffffu, mp, o);
        if (lane >= o) mp = max(mp, t);
    }
    if (lane == 31) part_b[wrp] = mp;
    __syncthreads();
    if (tid < 32) {
        int p = part_b[tid];
        #pragma unroll
        for (int o = 1; o < 32; o <<= 1) {
            int t = __shfl_up_sync(0xffffffffu, p, o);
            if (tid >= o) p = max(p, t);
        }
        part_b[tid] = p;
    }
    __syncthreads();
    if (wrp > 0) mp = max(mp, part_b[wrp - 1]);

    float y = mval[mp];            // pooled mean, clamped >= 0, nonincreasing in tid
    float z = sgn_i * y;           // oscar prox at sorted position tid

    // ---- sorted-z without a sort: packed (P,N) rank scan ----
    int fP = (z > 0.0f) ? 1 : 0;
    int fN = (z < 0.0f) ? 1 : 0;
    int pk = (fP << 16) | fN;
    int incl = bscan_add(pk, tid, lane, wrp, part_c);
    int excl = incl - pk;
    int totalP = __syncthreads_count(z > 0.0f);   // barrier + block-wide count

    int pPex = excl >> 16;
    int pNex = excl & 0xffff;
    int pos;
    if (z > 0.0f)      pos = pPex;                          // positives: i-order
    else if (z < 0.0f) pos = DD - 1 - pNex;                 // negatives: reverse i-order
    else               pos = totalP + (tid - pPex - pNex);  // zeros: middle
    zcs[pos] = z;
    __syncthreads();

    // ---- sparsemax: cumsum, support count, tau ----
    float zs_t = zcs[tid];
    float c = zs_t;
    #pragma unroll
    for (int o = 1; o < 32; o <<= 1) {
        float t = __shfl_up_sync(0xffffffffu, c, o);
        if (lane >= o) c += t;
    }
    if (lane == 31) part_d[wrp] = c;
    __syncthreads();
    if (tid < 32) {
        float p = part_d[tid];
        #pragma unroll
        for (int o = 1; o < 32; o <<= 1) {
            float t = __shfl_up_sync(0xffffffffu, p, o);
            if (tid >= o) p += t;
        }
        part_d[tid] = p;
    }
    __syncthreads();
    if (wrp > 0) c += part_d[wrp - 1];

    zcs[tid] = c;
    bool flagS = (1.0f + (float)(tid + 1) * zs_t) > c;
    int k_sup = __syncthreads_count(flagS);   // support is a prefix; also the barrier
    float tau = (zcs[k_sup - 1] - 1.0f) / (float)k_sup;

    out[row * DD + idx] = fmaxf(z - tau, 0.0f);
}

extern "C" void kernel_launch(void* const* d_in, const int* in_sizes, int n_in,
                              void* d_out, int out_size) {
    const float* x = (const float*)d_in[0];
    float* out = (float*)d_out;
    oscarmax_kernel<<<BB, DD>>>(x, out);
}